// round 3
// baseline (speedup 1.0000x reference)
#include <cuda_runtime.h>
#include <cuda_bf16.h>
#include <math_constants.h>

#define NN 1024
#define CC 8
#define DIM 128
#define KK 3
#define LBP_LOOPS 10

// ---------------- device scratch (allocation-free rule: static globals) ----------------
__device__ float g_phi[(size_t)NN * NN * CC * CC];   // 256 MB  phi[i][j][ci][cj]
__device__ float g_m0[(size_t)NN * NN * CC];         // 32 MB   mbar ping
__device__ float g_m1[(size_t)NN * NN * CC];         // 32 MB   mbar pong
__device__ float g_part[64 * NN * CC];               // 2 MB    per-i-tile partial column sums
__device__ float g_inc[2][NN * CC];                  // incoming[i][c], double-buffered
__device__ float g_psi[NN * CC];

// ---------------- utility ----------------
__global__ void zero_kernel(float* p, int n) {
    int idx = blockIdx.x * blockDim.x + threadIdx.x;
    int stride = gridDim.x * blockDim.x;
    for (; idx < n; idx += stride) p[idx] = 0.0f;
}

// psi[i,c] = sum_d E[i,c,d] * B[d] * Fc[i,d]
__global__ void psi_kernel(const float* __restrict__ E, const float* __restrict__ B,
                           const float* __restrict__ Fc) {
    int i = blockIdx.x;
    int w = threadIdx.x >> 5;     // warp = candidate c
    int lane = threadIdx.x & 31;
    const float* e  = E  + ((size_t)i * CC + w) * DIM;
    const float* fc = Fc + (size_t)i * DIM;
    float s = 0.0f;
    for (int d = lane; d < DIM; d += 32) s = fmaf(e[d] * B[d], fc[d], s);
    #pragma unroll
    for (int off = 16; off; off >>= 1) s += __shfl_xor_sync(0xffffffffu, s, off);
    if (lane == 0) g_psi[i * CC + w] = s;
}

// ---------------- phi build (fused logits -> softmax_k -> triple product) ----------------
// Tile 16 i x 16 j, 256 threads, one (i,j) pair per thread.
// smem layouts transposed so the tile index (ti/tj) is the fastest dim (conflict-free LDS).
#define SEI_SZ (CC * DIM * 17)          // 17408 floats
#define SFD_SZ (KK * DIM * 17)          // 6528
#define SFJ_SZ (DIM * 17)               // 2176
#define SR_SZ  (KK * DIM)               // 384
#define PHI_SMEM_FLOATS (2 * SEI_SZ + SFD_SZ + SFJ_SZ + SR_SZ)
#define PHI_SMEM_BYTES  (PHI_SMEM_FLOATS * 4)

__global__ void __launch_bounds__(256, 1)
phi_kernel(const float* __restrict__ E, const float* __restrict__ F,
           const float* __restrict__ R, const float* __restrict__ D) {
    extern __shared__ float sm[];
    float* sEi = sm;                 // [c*128+d][17] -> E[i0+ti][c][d]
    float* sEj = sEi + SEI_SZ;       // same for j tile
    float* sFD = sEj + SEI_SZ;       // [k*128+d][17] -> F[i0+ti][d]*D[k][d]
    float* sFj = sFD + SFD_SZ;       // [d][17]       -> F[j0+tj][d]
    float* sR  = sFj + SFJ_SZ;       // [k*128+d]

    const int tid = threadIdx.x;
    const int ti = tid >> 4, tj = tid & 15;
    const int i0 = blockIdx.y * 16, j0 = blockIdx.x * 16;

    // cooperative loads (coalesced global reads)
    for (int idx = tid; idx < 16 * CC * DIM; idx += 256) {
        int t = idx >> 10;            // which row of the tile
        int rem = idx & 1023;         // c*128+d
        sEi[rem * 17 + t] = E[((size_t)(i0 + t)) * (CC * DIM) + rem];
        sEj[rem * 17 + t] = E[((size_t)(j0 + t)) * (CC * DIM) + rem];
    }
    for (int idx = tid; idx < 16 * DIM; idx += 256) {
        int t = idx >> 7, d = idx & 127;
        float fi = F[(i0 + t) * DIM + d];
        sFj[d * 17 + t] = F[(j0 + t) * DIM + d];
        sFD[(0 * DIM + d) * 17 + t] = fi * D[0 * DIM + d];
        sFD[(1 * DIM + d) * 17 + t] = fi * D[1 * DIM + d];
        sFD[(2 * DIM + d) * 17 + t] = fi * D[2 * DIM + d];
    }
    for (int idx = tid; idx < SR_SZ; idx += 256) sR[idx] = R[idx];
    __syncthreads();

    // logits[i,j,k] = sum_d F[i,d]*D[k,d]*F[j,d] / sqrt(DIM); a = softmax_k
    float l0 = 0.f, l1 = 0.f, l2 = 0.f;
    #pragma unroll 4
    for (int d = 0; d < DIM; d++) {
        float fj = sFj[d * 17 + tj];
        l0 = fmaf(sFD[(0 * DIM + d) * 17 + ti], fj, l0);
        l1 = fmaf(sFD[(1 * DIM + d) * 17 + ti], fj, l1);
        l2 = fmaf(sFD[(2 * DIM + d) * 17 + ti], fj, l2);
    }
    const float rs = 0.08838834764831845f;   // 1/sqrt(128)
    l0 *= rs; l1 *= rs; l2 *= rs;
    float mx = fmaxf(l0, fmaxf(l1, l2));
    float a0 = __expf(l0 - mx), a1 = __expf(l1 - mx), a2 = __expf(l2 - mx);
    float inv = 1.0f / (a0 + a1 + a2);
    a0 *= inv; a1 *= inv; a2 *= inv;

    // phi[ci][cj] = sum_d Ei[ci,d] * (a.R)[d] * Ej[cj,d]
    float acc[CC][CC];
    #pragma unroll
    for (int ci = 0; ci < CC; ci++)
        #pragma unroll
        for (int cj = 0; cj < CC; cj++) acc[ci][cj] = 0.0f;

    #pragma unroll 2
    for (int d = 0; d < DIM; d++) {
        float rw = a0 * sR[d];
        rw = fmaf(a1, sR[DIM + d], rw);
        rw = fmaf(a2, sR[2 * DIM + d], rw);
        float ei[CC], wj[CC];
        #pragma unroll
        for (int c = 0; c < CC; c++) ei[c] = sEi[(c * DIM + d) * 17 + ti];
        #pragma unroll
        for (int c = 0; c < CC; c++) wj[c] = sEj[(c * DIM + d) * 17 + tj] * rw;
        #pragma unroll
        for (int ci = 0; ci < CC; ci++)
            #pragma unroll
            for (int cj = 0; cj < CC; cj++)
                acc[ci][cj] = fmaf(ei[ci], wj[cj], acc[ci][cj]);
    }

    float* outp = g_phi + (((size_t)(i0 + ti) << 10) + (j0 + tj)) * (CC * CC);
    #pragma unroll
    for (int ci = 0; ci < CC; ci++) {
        *(float4*)(outp + ci * CC)     = make_float4(acc[ci][0], acc[ci][1], acc[ci][2], acc[ci][3]);
        *(float4*)(outp + ci * CC + 4) = make_float4(acc[ci][4], acc[ci][5], acc[ci][6], acc[ci][7]);
    }
}

// ---------------- one LBP iteration ----------------
// msg[i,j,cj] = max_ci( psi[i,ci] + inc[i,ci] - mold[j,i,ci] + phi[i,j,ci,cj] )
// new[i,j,cj] = log( 0.5*softmax_cj(msg) + 0.5*exp(mold[i,j,cj]) )
// Also emits per-(i-tile) partial column sums of new -> g_part (deterministic).
__global__ void __launch_bounds__(256)
lbp_kernel(int t) {
    const float* mold = (t & 1) ? g_m1 : g_m0;
    float* mnew       = (t & 1) ? g_m0 : g_m1;
    const float* inc_cur = g_inc[t & 1];

    const int tid = threadIdx.x;
    const int ti = tid >> 4, tj = tid & 15;
    const int i = blockIdx.y * 16 + ti;
    const int j = blockIdx.x * 16 + tj;
    const size_t pij = ((size_t)i << 10) + j;
    const size_t pji = ((size_t)j << 10) + i;

    float4 mt0 = *(const float4*)(mold + pji * CC);
    float4 mt1 = *(const float4*)(mold + pji * CC + 4);
    float4 q0  = *(const float4*)(g_psi + i * CC);
    float4 q1  = *(const float4*)(g_psi + i * CC + 4);
    float4 ic0 = *(const float4*)(inc_cur + i * CC);
    float4 ic1 = *(const float4*)(inc_cur + i * CC + 4);

    float base[CC];
    base[0] = q0.x + ic0.x - mt0.x;  base[1] = q0.y + ic0.y - mt0.y;
    base[2] = q0.z + ic0.z - mt0.z;  base[3] = q0.w + ic0.w - mt0.w;
    base[4] = q1.x + ic1.x - mt1.x;  base[5] = q1.y + ic1.y - mt1.y;
    base[6] = q1.z + ic1.z - mt1.z;  base[7] = q1.w + ic1.w - mt1.w;

    float msg[CC];
    #pragma unroll
    for (int c = 0; c < CC; c++) msg[c] = -CUDART_INF_F;

    const float4* ph = (const float4*)(g_phi + pij * (CC * CC));
    #pragma unroll
    for (int ci = 0; ci < CC; ci++) {
        float4 p0 = ph[ci * 2];
        float4 p1 = ph[ci * 2 + 1];
        float b = base[ci];
        msg[0] = fmaxf(msg[0], b + p0.x);  msg[1] = fmaxf(msg[1], b + p0.y);
        msg[2] = fmaxf(msg[2], b + p0.z);  msg[3] = fmaxf(msg[3], b + p0.w);
        msg[4] = fmaxf(msg[4], b + p1.x);  msg[5] = fmaxf(msg[5], b + p1.y);
        msg[6] = fmaxf(msg[6], b + p1.z);  msg[7] = fmaxf(msg[7], b + p1.w);
    }

    float m = msg[0];
    #pragma unroll
    for (int c = 1; c < CC; c++) m = fmaxf(m, msg[c]);
    float s[CC], Z = 0.f;
    #pragma unroll
    for (int c = 0; c < CC; c++) { s[c] = __expf(msg[c] - m); Z += s[c]; }
    float k0 = 0.5f / Z;

    float4 o0 = *(const float4*)(mold + pij * CC);
    float4 o1 = *(const float4*)(mold + pij * CC + 4);
    float oldv[CC] = {o0.x, o0.y, o0.z, o0.w, o1.x, o1.y, o1.z, o1.w};

    float nv[CC];
    #pragma unroll
    for (int c = 0; c < CC; c++)
        nv[c] = __logf(fmaf(s[c], k0, 0.5f * __expf(oldv[c])));

    *(float4*)(mnew + pij * CC)     = make_float4(nv[0], nv[1], nv[2], nv[3]);
    *(float4*)(mnew + pij * CC + 4) = make_float4(nv[4], nv[5], nv[6], nv[7]);

    // ---- partial column sums: sum over this block's 16 i for each (j, cj) ----
    float r[CC];
    #pragma unroll
    for (int c = 0; c < CC; c++)
        r[c] = nv[c] + __shfl_xor_sync(0xffffffffu, nv[c], 16);  // pair ti's within warp

    __shared__ float sPart[8][16][CC];
    int w = tid >> 5, lane = tid & 31;
    if (lane < 16) {
        #pragma unroll
        for (int c = 0; c < CC; c++) sPart[w][lane][c] = r[c];
    }
    __syncthreads();
    if (tid < 128) {
        int tj2 = tid >> 3, c = tid & 7;
        float sum = 0.f;
        #pragma unroll
        for (int w2 = 0; w2 < 8; w2++) sum += sPart[w2][tj2][c];
        g_part[((size_t)blockIdx.y * NN + (blockIdx.x * 16 + tj2)) * CC + c] = sum;
    }
}

// inc_next[j,c] = sum over 64 i-tiles of g_part  (deterministic fixed-order sum)
__global__ void reduce_kernel(int t) {
    float* inc_next = g_inc[(t + 1) & 1];
    int idx = blockIdx.x * blockDim.x + threadIdx.x;   // 0..8191
    if (idx < NN * CC) {
        float ssum = 0.f;
        #pragma unroll
        for (int b = 0; b < 64; b++) ssum += g_part[(size_t)b * NN * CC + idx];
        inc_next[idx] = ssum;
    }
}

// u[i,c] = psi + colsum(mbar) - mbar[i,i,c]; out = softmax_c(u)
__global__ void final_kernel(float* __restrict__ out) {
    int i = blockIdx.x * blockDim.x + threadIdx.x;
    if (i >= NN) return;
    const float* inc_f = g_inc[0];          // after t=9 (odd), next buffer = g_inc[0]
    const float* mf = g_m0;                 // t=9 writes g_m0
    size_t self = (((size_t)i << 10) + i) * CC;
    float u[CC], m = -CUDART_INF_F;
    #pragma unroll
    for (int c = 0; c < CC; c++) {
        u[c] = g_psi[i * CC + c] + inc_f[i * CC + c] - mf[self + c];
        m = fmaxf(m, u[c]);
    }
    float Z = 0.f;
    #pragma unroll
    for (int c = 0; c < CC; c++) { u[c] = __expf(u[c] - m); Z += u[c]; }
    float inv = 1.0f / Z;
    #pragma unroll
    for (int c = 0; c < CC; c++) out[i * CC + c] = u[c] * inv;
}

// ---------------- host launcher ----------------
extern "C" void kernel_launch(void* const* d_in, const int* in_sizes, int n_in,
                              void* d_out, int out_size) {
    const float* E  = (const float*)d_in[0];
    const float* F  = (const float*)d_in[1];
    const float* Fc = (const float*)d_in[2];
    const float* B  = (const float*)d_in[3];
    const float* R  = (const float*)d_in[4];
    const float* D  = (const float*)d_in[5];
    float* out = (float*)d_out;

    // sticky attribute; ignore failure during capture (already set on first call)
    (void)cudaFuncSetAttribute(phi_kernel, cudaFuncAttributeMaxDynamicSharedMemorySize,
                               PHI_SMEM_BYTES);

    float* m0p;   (void)cudaGetSymbolAddress((void**)&m0p, g_m0);
    float* incp;  (void)cudaGetSymbolAddress((void**)&incp, g_inc);

    zero_kernel<<<1024, 256>>>(m0p, NN * NN * CC);        // mbar_0 = 0
    zero_kernel<<<8, 256>>>(incp, NN * CC);               // incoming_0 = 0

    psi_kernel<<<NN, 256>>>(E, B, Fc);

    dim3 tiles(64, 64);
    phi_kernel<<<tiles, 256, PHI_SMEM_BYTES>>>(E, F, R, D);

    for (int t = 0; t < LBP_LOOPS; t++) {
        lbp_kernel<<<tiles, 256>>>(t);
        reduce_kernel<<<32, 256>>>(t);
    }

    final_kernel<<<4, 256>>>(out);
}

// round 4
// speedup vs baseline: 1.0502x; 1.0502x over previous
#include <cuda_runtime.h>
#include <cuda_bf16.h>
#include <math_constants.h>

#define NN 1024
#define CC 8
#define DIM 128
#define KK 3
#define LBP_LOOPS 10

typedef unsigned long long ull;

// ---------------- device scratch (allocation-free rule: static globals) ----------------
__device__ float g_phi[(size_t)NN * NN * CC * CC];   // 256 MB  phi[i][j][ci][cj]
__device__ float g_m0[(size_t)NN * NN * CC];         // 32 MB   mbar ping
__device__ float g_m1[(size_t)NN * NN * CC];         // 32 MB   mbar pong
__device__ float g_part[64 * NN * CC];               // 2 MB    per-i-tile partial column sums
__device__ float g_inc[2][NN * CC];                  // incoming[i][c], double-buffered
__device__ float g_psi[NN * CC];

// ---------------- f32x2 packed-math helpers (FFMA2 — ptxas never emits this itself) ----
__device__ __forceinline__ ull pk2(float x, float y) {
    ull r; asm("mov.b64 %0, {%1,%2};" : "=l"(r) : "f"(x), "f"(y)); return r;
}
__device__ __forceinline__ void upk2(ull v, float& x, float& y) {
    asm("mov.b64 {%0,%1}, %2;" : "=f"(x), "=f"(y) : "l"(v));
}
__device__ __forceinline__ ull fma2(ull a, ull b, ull c) {
    ull d; asm("fma.rn.f32x2 %0, %1, %2, %3;" : "=l"(d) : "l"(a), "l"(b), "l"(c)); return d;
}
__device__ __forceinline__ ull mul2(ull a, ull b) {
    ull d; asm("mul.rn.f32x2 %0, %1, %2;" : "=l"(d) : "l"(a), "l"(b)); return d;
}

// ---------------- utility ----------------
__global__ void zero_kernel(float* p, int n) {
    int idx = blockIdx.x * blockDim.x + threadIdx.x;
    int stride = gridDim.x * blockDim.x;
    for (; idx < n; idx += stride) p[idx] = 0.0f;
}

// psi[i,c] = sum_d E[i,c,d] * B[d] * Fc[i,d]
__global__ void psi_kernel(const float* __restrict__ E, const float* __restrict__ B,
                           const float* __restrict__ Fc) {
    int i = blockIdx.x;
    int w = threadIdx.x >> 5;
    int lane = threadIdx.x & 31;
    const float* e  = E  + ((size_t)i * CC + w) * DIM;
    const float* fc = Fc + (size_t)i * DIM;
    float s = 0.0f;
    for (int d = lane; d < DIM; d += 32) s = fmaf(e[d] * B[d], fc[d], s);
    #pragma unroll
    for (int off = 16; off; off >>= 1) s += __shfl_xor_sync(0xffffffffu, s, off);
    if (lane == 0) g_psi[i * CC + w] = s;
}

// ---------------- phi build: fused logits -> softmax_k -> triple product, FFMA2 core ----
// Tile 16 i x 16 j, 256 threads, one (i,j) pair per thread.
// E tiles stored t-major, row stride 1026 floats (even -> 8B-aligned float2;
// 1026 mod 32 = 2 -> the two ti half-warps hit different banks).
#define STRE  (CC * DIM + 2)    // 1026
#define STRFD (KK * DIM + 2)    // 386
#define STRF  (DIM + 2)         // 130
#define SEI_SZ (16 * STRE)      // 16416
#define SFD_SZ (16 * STRFD)     // 6176
#define SFJ_SZ (16 * STRF)      // 2080
#define SR_SZ  (KK * DIM)       // 384
#define PHI_SMEM_FLOATS (2 * SEI_SZ + SFD_SZ + SFJ_SZ + SR_SZ)
#define PHI_SMEM_BYTES  (PHI_SMEM_FLOATS * 4)

__global__ void __launch_bounds__(256, 1)
phi_kernel(const float* __restrict__ E, const float* __restrict__ F,
           const float* __restrict__ R, const float* __restrict__ D) {
    extern __shared__ float sm[];
    float* sEi = sm;                 // [t][c*128+d]
    float* sEj = sEi + SEI_SZ;       // [t][c*128+d]
    float* sFD = sEj + SEI_SZ;       // [t][k*128+d] = F[i0+t][d]*D[k][d]
    float* sFj = sFD + SFD_SZ;       // [t][d]
    float* sR  = sFj + SFJ_SZ;       // [k*128+d]

    const int tid = threadIdx.x;
    const int ti = tid >> 4, tj = tid & 15;
    const int i0 = blockIdx.y * 16, j0 = blockIdx.x * 16;

    // cooperative loads (coalesced global reads, consecutive smem banks)
    for (int idx = tid; idx < 16 * CC * DIM; idx += 256) {
        int t = idx >> 10;            // tile row
        int rem = idx & 1023;         // c*128+d
        sEi[t * STRE + rem] = E[((size_t)(i0 + t)) * (CC * DIM) + rem];
        sEj[t * STRE + rem] = E[((size_t)(j0 + t)) * (CC * DIM) + rem];
    }
    for (int idx = tid; idx < 16 * DIM; idx += 256) {
        int t = idx >> 7, d = idx & 127;
        float fi = F[(i0 + t) * DIM + d];
        sFj[t * STRF + d] = F[(j0 + t) * DIM + d];
        sFD[t * STRFD + 0 * DIM + d] = fi * D[0 * DIM + d];
        sFD[t * STRFD + 1 * DIM + d] = fi * D[1 * DIM + d];
        sFD[t * STRFD + 2 * DIM + d] = fi * D[2 * DIM + d];
    }
    for (int idx = tid; idx < SR_SZ; idx += 256) sR[idx] = R[idx];
    __syncthreads();

    // logits[k] = sum_d Fi[d]*D[k,d]*Fj[d] / sqrt(DIM); a = softmax_k  (f32x2 pairs over d)
    const ull* pFj = (const ull*)(sFj + tj * STRF);
    const ull* pFD = (const ull*)(sFD + ti * STRFD);
    ull L0 = 0ull, L1 = 0ull, L2 = 0ull;
    #pragma unroll 8
    for (int h = 0; h < DIM / 2; h++) {
        ull fj = pFj[h];
        L0 = fma2(pFD[h],              fj, L0);
        L1 = fma2(pFD[DIM / 2 + h],    fj, L1);
        L2 = fma2(pFD[DIM + h],        fj, L2);
    }
    float x0, y0, x1, y1, x2, y2;
    upk2(L0, x0, y0); upk2(L1, x1, y1); upk2(L2, x2, y2);
    const float rs = 0.08838834764831845f;   // 1/sqrt(128)
    float l0 = (x0 + y0) * rs, l1 = (x1 + y1) * rs, l2 = (x2 + y2) * rs;
    float mx = fmaxf(l0, fmaxf(l1, l2));
    float a0 = __expf(l0 - mx), a1 = __expf(l1 - mx), a2 = __expf(l2 - mx);
    float inv = 1.0f / (a0 + a1 + a2);
    a0 *= inv; a1 *= inv; a2 *= inv;

    // phi[ci][cj] = sum_d Ei[ci,d] * (a.R)[d] * Ej[cj,d]   — FFMA2 over d-pairs
    ull acc[CC][CC];
    #pragma unroll
    for (int ci = 0; ci < CC; ci++)
        #pragma unroll
        for (int cj = 0; cj < CC; cj++) acc[ci][cj] = 0ull;   // (0.0f, 0.0f)

    const ull A0 = pk2(a0, a0), A1 = pk2(a1, a1), A2 = pk2(a2, a2);
    const ull* pR  = (const ull*)sR;
    const ull* pEi = (const ull*)(sEi + ti * STRE);
    const ull* pEj = (const ull*)(sEj + tj * STRE);

    #pragma unroll 2
    for (int h = 0; h < DIM / 2; h++) {
        ull rw = mul2(A0, pR[h]);
        rw = fma2(A1, pR[DIM / 2 + h], rw);
        rw = fma2(A2, pR[DIM + h], rw);
        ull ei2[CC], wj2[CC];
        #pragma unroll
        for (int c = 0; c < CC; c++) ei2[c] = pEi[c * (DIM / 2) + h];
        #pragma unroll
        for (int c = 0; c < CC; c++) wj2[c] = mul2(pEj[c * (DIM / 2) + h], rw);
        #pragma unroll
        for (int ci = 0; ci < CC; ci++)
            #pragma unroll
            for (int cj = 0; cj < CC; cj++)
                acc[ci][cj] = fma2(ei2[ci], wj2[cj], acc[ci][cj]);
    }

    float* outp = g_phi + (((size_t)(i0 + ti) << 10) + (j0 + tj)) * (CC * CC);
    #pragma unroll
    for (int ci = 0; ci < CC; ci++) {
        float v[CC];
        #pragma unroll
        for (int cj = 0; cj < CC; cj++) {
            float lo, hi; upk2(acc[ci][cj], lo, hi); v[cj] = lo + hi;
        }
        *(float4*)(outp + ci * CC)     = make_float4(v[0], v[1], v[2], v[3]);
        *(float4*)(outp + ci * CC + 4) = make_float4(v[4], v[5], v[6], v[7]);
    }
}

// ---------------- one LBP iteration ----------------
// msg[i,j,cj] = max_ci( psi[i,ci] + inc[i,ci] - mold[j,i,ci] + phi[i,j,ci,cj] )
// new[i,j,cj] = log( 0.5*softmax_cj(msg) + 0.5*exp(mold[i,j,cj]) )
__global__ void __launch_bounds__(256)
lbp_kernel(int t) {
    const float* mold = (t & 1) ? g_m1 : g_m0;
    float* mnew       = (t & 1) ? g_m0 : g_m1;
    const float* inc_cur = g_inc[t & 1];

    const int tid = threadIdx.x;
    const int ti = tid >> 4, tj = tid & 15;
    const int i = blockIdx.y * 16 + ti;
    const int j = blockIdx.x * 16 + tj;
    const size_t pij = ((size_t)i << 10) + j;
    const size_t pji = ((size_t)j << 10) + i;

    float4 mt0 = *(const float4*)(mold + pji * CC);
    float4 mt1 = *(const float4*)(mold + pji * CC + 4);
    float4 q0  = *(const float4*)(g_psi + i * CC);
    float4 q1  = *(const float4*)(g_psi + i * CC + 4);
    float4 ic0 = *(const float4*)(inc_cur + i * CC);
    float4 ic1 = *(const float4*)(inc_cur + i * CC + 4);

    float base[CC];
    base[0] = q0.x + ic0.x - mt0.x;  base[1] = q0.y + ic0.y - mt0.y;
    base[2] = q0.z + ic0.z - mt0.z;  base[3] = q0.w + ic0.w - mt0.w;
    base[4] = q1.x + ic1.x - mt1.x;  base[5] = q1.y + ic1.y - mt1.y;
    base[6] = q1.z + ic1.z - mt1.z;  base[7] = q1.w + ic1.w - mt1.w;

    float msg[CC];
    #pragma unroll
    for (int c = 0; c < CC; c++) msg[c] = -CUDART_INF_F;

    const float4* ph = (const float4*)(g_phi + pij * (CC * CC));
    #pragma unroll
    for (int ci = 0; ci < CC; ci++) {
        float4 p0 = ph[ci * 2];
        float4 p1 = ph[ci * 2 + 1];
        float b = base[ci];
        msg[0] = fmaxf(msg[0], b + p0.x);  msg[1] = fmaxf(msg[1], b + p0.y);
        msg[2] = fmaxf(msg[2], b + p0.z);  msg[3] = fmaxf(msg[3], b + p0.w);
        msg[4] = fmaxf(msg[4], b + p1.x);  msg[5] = fmaxf(msg[5], b + p1.y);
        msg[6] = fmaxf(msg[6], b + p1.z);  msg[7] = fmaxf(msg[7], b + p1.w);
    }

    float m = msg[0];
    #pragma unroll
    for (int c = 1; c < CC; c++) m = fmaxf(m, msg[c]);
    float s[CC], Z = 0.f;
    #pragma unroll
    for (int c = 0; c < CC; c++) { s[c] = __expf(msg[c] - m); Z += s[c]; }
    float k0 = 0.5f / Z;

    float4 o0 = *(const float4*)(mold + pij * CC);
    float4 o1 = *(const float4*)(mold + pij * CC + 4);
    float oldv[CC] = {o0.x, o0.y, o0.z, o0.w, o1.x, o1.y, o1.z, o1.w};

    float nv[CC];
    #pragma unroll
    for (int c = 0; c < CC; c++)
        nv[c] = __logf(fmaf(s[c], k0, 0.5f * __expf(oldv[c])));

    *(float4*)(mnew + pij * CC)     = make_float4(nv[0], nv[1], nv[2], nv[3]);
    *(float4*)(mnew + pij * CC + 4) = make_float4(nv[4], nv[5], nv[6], nv[7]);

    // ---- partial column sums over this block's 16 i, per (j, cj) — deterministic ----
    float r[CC];
    #pragma unroll
    for (int c = 0; c < CC; c++)
        r[c] = nv[c] + __shfl_xor_sync(0xffffffffu, nv[c], 16);

    __shared__ float sPart[8][16][CC];
    int w = tid >> 5, lane = tid & 31;
    if (lane < 16) {
        #pragma unroll
        for (int c = 0; c < CC; c++) sPart[w][lane][c] = r[c];
    }
    __syncthreads();
    if (tid < 128) {
        int tj2 = tid >> 3, c = tid & 7;
        float sum = 0.f;
        #pragma unroll
        for (int w2 = 0; w2 < 8; w2++) sum += sPart[w2][tj2][c];
        g_part[((size_t)blockIdx.y * NN + (blockIdx.x * 16 + tj2)) * CC + c] = sum;
    }
}

// inc_next[j,c] = sum over 64 i-tiles of g_part  (fixed-order, deterministic)
__global__ void reduce_kernel(int t) {
    float* inc_next = g_inc[(t + 1) & 1];
    int idx = blockIdx.x * blockDim.x + threadIdx.x;
    if (idx < NN * CC) {
        float ssum = 0.f;
        #pragma unroll
        for (int b = 0; b < 64; b++) ssum += g_part[(size_t)b * NN * CC + idx];
        inc_next[idx] = ssum;
    }
}

// u[i,c] = psi + colsum(mbar) - mbar[i,i,c]; out = softmax_c(u)
__global__ void final_kernel(float* __restrict__ out) {
    int i = blockIdx.x * blockDim.x + threadIdx.x;
    if (i >= NN) return;
    const float* inc_f = g_inc[0];          // after t=9 (odd), next buffer = g_inc[0]
    const float* mf = g_m0;                 // t=9 writes g_m0
    size_t self = (((size_t)i << 10) + i) * CC;
    float u[CC], m = -CUDART_INF_F;
    #pragma unroll
    for (int c = 0; c < CC; c++) {
        u[c] = g_psi[i * CC + c] + inc_f[i * CC + c] - mf[self + c];
        m = fmaxf(m, u[c]);
    }
    float Z = 0.f;
    #pragma unroll
    for (int c = 0; c < CC; c++) { u[c] = __expf(u[c] - m); Z += u[c]; }
    float inv = 1.0f / Z;
    #pragma unroll
    for (int c = 0; c < CC; c++) out[i * CC + c] = u[c] * inv;
}

// ---------------- host launcher ----------------
extern "C" void kernel_launch(void* const* d_in, const int* in_sizes, int n_in,
                              void* d_out, int out_size) {
    const float* E  = (const float*)d_in[0];
    const float* F  = (const float*)d_in[1];
    const float* Fc = (const float*)d_in[2];
    const float* B  = (const float*)d_in[3];
    const float* R  = (const float*)d_in[4];
    const float* D  = (const float*)d_in[5];
    float* out = (float*)d_out;

    (void)cudaFuncSetAttribute(phi_kernel, cudaFuncAttributeMaxDynamicSharedMemorySize,
                               PHI_SMEM_BYTES);

    float* m0p;   (void)cudaGetSymbolAddress((void**)&m0p, g_m0);
    float* incp;  (void)cudaGetSymbolAddress((void**)&incp, g_inc);

    zero_kernel<<<1024, 256>>>(m0p, NN * NN * CC);        // mbar_0 = 0
    zero_kernel<<<8, 256>>>(incp, NN * CC);               // incoming_0 = 0

    psi_kernel<<<NN, 256>>>(E, B, Fc);

    dim3 tiles(64, 64);
    phi_kernel<<<tiles, 256, PHI_SMEM_BYTES>>>(E, F, R, D);

    for (int t = 0; t < LBP_LOOPS; t++) {
        lbp_kernel<<<tiles, 256>>>(t);
        reduce_kernel<<<32, 256>>>(t);
    }

    final_kernel<<<4, 256>>>(out);
}